// round 10
// baseline (speedup 1.0000x reference)
#include <cuda_runtime.h>
#include <cuda_fp16.h>
#include <cstdint>

// ---------------------------------------------------------------------------
// W4A16 grouped GEMM: out[32,28672] = x[32,8192] @ dequant(qweight) + bias
//   qweight int32 [K/8, N]: 8 int4 nibbles per word along K, zero-point 8
//   x / scales / bias fp16-origin delivered as f32; output f32.
//
// R10: 256 threads/CTA (8 warps x 16 n-cols each), split-K x8, fused
// last-CTA reduction. Halves per-thread register state vs R8/R9 (acc 32->16,
// frag 17->9) so NO __launch_bounds__ reg cap is needed -> no spills
// (R9 regression root cause: cap to 80 regs spilled the inner loop, L1 60%).
// Single __syncthreads per chunk; distance-2 LDG prefetch.
//
// Inner math unchanged: mma.sync.m16n8k16 + ldmatrix; qweight words
// LDS-broadcast, dequantized into B frags via byte_perm + magic-bias +
// exact HSUB2{1032,1152} / HMUL2{s,s/16} -> single fp16 rounding per weight.
// ---------------------------------------------------------------------------

static constexpr int MDIM    = 32;
static constexpr int KDIM    = 8192;
static constexpr int NDIM    = 28672;
static constexpr int NT      = 128;                 // n per CTA tile
static constexpr int KC      = 64;                  // k per chunk
static constexpr int KSPLIT  = 8;
static constexpr int CPS     = KDIM / KC / KSPLIT;  // 16 chunks per split
static constexpr int NTILES  = NDIM / NT;           // 224
static constexpr int THREADS = 256;                 // 8 warps
static constexpr int XSTRIDE = 144;                 // bytes per x row in SMEM

__device__ float g_scratch[KSPLIT * MDIM * NDIM];   // 29.36 MB partials
__device__ int   g_cnt[NTILES];                     // zero-init; reset after use

// --------------------------- PTX helpers -----------------------------------

__device__ __forceinline__ uint32_t smem_u32(const void* p) {
    uint32_t a;
    asm("{ .reg .u64 t; cvta.to.shared.u64 t, %1; cvt.u32.u64 %0, t; }"
        : "=r"(a) : "l"(p));
    return a;
}

__device__ __forceinline__ void ldmatrix_x4(uint32_t* r, uint32_t addr) {
    asm volatile(
        "ldmatrix.sync.aligned.m8n8.x4.shared.b16 {%0,%1,%2,%3}, [%4];"
        : "=r"(r[0]), "=r"(r[1]), "=r"(r[2]), "=r"(r[3]) : "r"(addr));
}

__device__ __forceinline__ void mma_16816(float* c, const uint32_t* a,
                                          uint32_t b0, uint32_t b1) {
    asm volatile(
        "mma.sync.aligned.m16n8k16.row.col.f32.f16.f16.f32 "
        "{%0,%1,%2,%3}, {%4,%5,%6,%7}, {%8,%9}, {%0,%1,%2,%3};"
        : "+f"(c[0]), "+f"(c[1]), "+f"(c[2]), "+f"(c[3])
        : "r"(a[0]), "r"(a[1]), "r"(a[2]), "r"(a[3]), "r"(b0), "r"(b1));
}

__device__ __forceinline__ uint32_t pack_h2(float a, float b) {
    __half2 h = __floats2half2_rn(a, b);
    return *reinterpret_cast<uint32_t*>(&h);
}

// --------------------------- dequant ---------------------------------------
// Byte t of word w holds (k=2t lo-nibble, k=2t+1 hi-nibble). byte_perm
// replicates byte t into bytes 0,2; mask+OR builds {1024+n_lo, 1024+16*n_hi};
// exact HSUB2 {1032,1152} then HMUL2 {s, s/16} -> {(n_lo-8)s, (n_hi-8)s}.
__device__ __forceinline__ uint32_t dq_pair(uint32_t w, uint32_t sel, uint32_t mul2u) {
    const uint32_t SUBC = 0x64806408u;  // half2 {1032, 1152}
    uint32_t v = __byte_perm(w, 0, sel);
    uint32_t p = (v & 0x00F0000Fu) | 0x64006400u;
    __half2 h = __hmul2(__hsub2(*reinterpret_cast<__half2*>(&p),
                                *reinterpret_cast<const __half2*>(&SUBC)),
                        *reinterpret_cast<__half2*>(&mul2u));
    return *reinterpret_cast<uint32_t*>(&h);
}

// --------------------------- prefetch fragment ------------------------------
// 256 threads split the chunk staging: 1 uint4 of qweight (4 words),
// 1 x row-piece (8 f32 -> 8 halfs), 1 scale. ~9 registers live.

struct Frag {
    uint4    qa;        // 4 qweight words: row tid>>5, word cols (tid&31)*4
    uint32_t xh[4];     // 8 halfs: x row tid>>3, k = c*64 + (tid&7)*8 ..
    float    sc;        // scales[c/2][n0 + (tid&127)]
};

__device__ __forceinline__ Frag load_frag(int c, const uint4* __restrict__ qw4,
                                          const float4* __restrict__ x4,
                                          const float* __restrict__ scales,
                                          int tid, int n0) {
    Frag f;
    int qi = (c * 8 + (tid >> 5)) * (NDIM / 4) + (n0 >> 2) + (tid & 31);
    f.qa = qw4[qi];
    int xi = (tid >> 3) * (KDIM / 4) + c * 16 + (tid & 7) * 2;
    float4 a0 = x4[xi], a1 = x4[xi + 1];
    f.xh[0] = pack_h2(a0.x, a0.y); f.xh[1] = pack_h2(a0.z, a0.w);
    f.xh[2] = pack_h2(a1.x, a1.y); f.xh[3] = pack_h2(a1.z, a1.w);
    f.sc = scales[(c >> 1) * NDIM + n0 + (tid & 127)];
    return f;
}

// --------------------------- main kernel ------------------------------------

__global__ void __launch_bounds__(THREADS)
w4a16_partial_kernel(const float* __restrict__ x,
                     const uint32_t* __restrict__ qweight,
                     const float* __restrict__ scales,
                     const float* __restrict__ bias,
                     float* __restrict__ out) {
    __shared__ uint32_t s_qw[2][8 * 128];                    // 8 KB
    __shared__ __align__(16) uint8_t s_x[2][32 * XSTRIDE];   // 9 KB
    __shared__ __half s_sc[2][128];
    __shared__ int s_last;

    const int tid  = threadIdx.x;
    const int lane = tid & 31;
    const int wid  = tid >> 5;                   // 0..7
    const int tile = blockIdx.x;
    const int n0   = tile * NT;
    const int ks   = blockIdx.y;
    const int c0   = ks * CPS;
    const int t4   = lane & 3;
    const uint32_t sel = 0x4040u + (uint32_t)t4 * 0x0101u;

    int nl[2];
#pragma unroll
    for (int j = 0; j < 2; ++j) nl[j] = wid * 16 + (lane >> 2) + 8 * j;

    const uint4*  qw4 = reinterpret_cast<const uint4*>(qweight);
    const float4* x4  = reinterpret_cast<const float4*>(x);
    const __half one16 = __ushort_as_half(0x2C00);   // 1/16

    uint32_t* qdst = &s_qw[0][(tid >> 5) * 128 + (tid & 31) * 4];
    uint8_t*  xdst = &s_x[0][(tid >> 3) * XSTRIDE + (tid & 7) * 16];
    const uint32_t xm_base = smem_u32(&s_x[0][0]) +
                             (uint32_t)(lane & 15) * XSTRIDE + (uint32_t)(lane >> 4) * 16;

    float acc[2][2][4];
#pragma unroll
    for (int mt = 0; mt < 2; ++mt)
#pragma unroll
        for (int j = 0; j < 2; ++j)
#pragma unroll
            for (int r = 0; r < 4; ++r) acc[mt][j][r] = 0.0f;

    // prologue: stage chunk 0 into buf0, prefetch chunk 1
    {
        Frag f0 = load_frag(c0, qw4, x4, scales, tid, n0);
        *reinterpret_cast<uint4*>(qdst) = f0.qa;
        *reinterpret_cast<uint4*>(xdst) = *reinterpret_cast<uint4*>(&f0.xh[0]);
        s_sc[0][tid & 127] = __float2half(f0.sc);
    }
    Frag pf = load_frag(c0 + 1, qw4, x4, scales, tid, n0);

    for (int ci = 0; ci < CPS; ++ci) {
        const int buf = ci & 1;
        __syncthreads();   // buf valid for compute; buf^1 free for store

        // store chunk ci+1 into buf^1 (final iteration's store never read)
        *reinterpret_cast<uint4*>(qdst + (buf ^ 1) * (8 * 128)) = pf.qa;
        *reinterpret_cast<uint4*>(xdst + (buf ^ 1) * (32 * XSTRIDE)) =
            *reinterpret_cast<uint4*>(&pf.xh[0]);
        s_sc[buf ^ 1][tid & 127] = __float2half(pf.sc);

        // prefetch chunk ci+2 (wrap within split; never consumed when wrapped)
        pf = load_frag(c0 + ((ci + 2) & (CPS - 1)), qw4, x4, scales, tid, n0);

        // compute chunk ci from buf
        uint32_t mul2[2];
#pragma unroll
        for (int j = 0; j < 2; ++j) {
            __half s = s_sc[buf][nl[j]];
            __half2 m = __halves2half2(s, __hmul(s, one16));
            mul2[j] = *reinterpret_cast<uint32_t*>(&m);
        }
        const uint32_t* qs = &s_qw[buf][0];
        const uint32_t xb = xm_base + (uint32_t)buf * (32 * XSTRIDE);

#pragma unroll
        for (int s4 = 0; s4 < 4; ++s4) {
            uint32_t a0[4], a1[4];
            ldmatrix_x4(a0, xb + s4 * 32);                    // m rows 0-15
            ldmatrix_x4(a1, xb + s4 * 32 + 16 * XSTRIDE);     // m rows 16-31
#pragma unroll
            for (int j = 0; j < 2; ++j) {
                uint32_t w0 = qs[(2 * s4)     * 128 + nl[j]];
                uint32_t w1 = qs[(2 * s4 + 1) * 128 + nl[j]];
                uint32_t b0 = dq_pair(w0, sel, mul2[j]);      // k = 2t, 2t+1
                uint32_t b1 = dq_pair(w1, sel, mul2[j]);      // k = 2t+8, 2t+9
                mma_16816(acc[0][j], a0, b0, b1);
                mma_16816(acc[1][j], a1, b0, b1);
            }
        }
    }

    // partial epilogue: raw f32 sums to scratch[ks][m][n]
    float* sp = g_scratch + ks * (MDIM * NDIM);
#pragma unroll
    for (int j = 0; j < 2; ++j) {
        const int n = n0 + wid * 16 + j * 8 + 2 * t4;
#pragma unroll
        for (int mt = 0; mt < 2; ++mt) {
            const int m0 = mt * 16 + (lane >> 2);
            float2 v01 = { acc[mt][j][0], acc[mt][j][1] };
            float2 v23 = { acc[mt][j][2], acc[mt][j][3] };
            *reinterpret_cast<float2*>(sp + m0 * NDIM + n)       = v01;
            *reinterpret_cast<float2*>(sp + (m0 + 8) * NDIM + n) = v23;
        }
    }

    // ---- fused reduction: last CTA of this tile sums the 8 partials --------
    __threadfence();
    if (tid == 0) {
        int old = atomicAdd(&g_cnt[tile], 1);
        s_last = (old == KSPLIT - 1);
    }
    __syncthreads();
    if (!s_last) return;

    if (tid == 0) g_cnt[tile] = 0;   // reset for next launch / graph replay
    __threadfence();                 // acquire: counter observation -> loads

    // 256 threads: col = tid&127, m-half = tid>>7 (16 m rows each)
    const int n  = n0 + (tid & 127);
    const int mh = (tid >> 7) * 16;
    const __half hb = __float2half(bias[n]);
    const float* sp0 = g_scratch + n;
#pragma unroll 4
    for (int m = mh; m < mh + 16; ++m) {
        float s = 0.0f;
#pragma unroll
        for (int k = 0; k < KSPLIT; ++k)
            s += sp0[(k * MDIM + m) * NDIM];
        out[m * NDIM + n] = __half2float(__hadd(__float2half(s), hb));
    }
}

// --------------------------- launch ------------------------------------------

extern "C" void kernel_launch(void* const* d_in, const int* in_sizes, int n_in,
                              void* d_out, int out_size) {
    (void)out_size;
    const float*    x    = nullptr;   // 262144
    const uint32_t* qw   = nullptr;   // 29360128
    const float*    sc   = nullptr;   // 1835008
    const float*    bias = nullptr;   // 28672
    for (int i = 0; i < n_in; ++i) {
        switch (in_sizes[i]) {
            case MDIM * KDIM:            x    = (const float*)d_in[i];    break;
            case (KDIM / 8) * NDIM:      qw   = (const uint32_t*)d_in[i]; break;
            case (KDIM / 128) * NDIM:    sc   = (const float*)d_in[i];    break;
            case NDIM:                   bias = (const float*)d_in[i];    break;
            default: break;
        }
    }
    float* out = (float*)d_out;

    dim3 grid(NTILES, KSPLIT);   // (224, 8) = 1792 CTAs
    w4a16_partial_kernel<<<grid, THREADS>>>(x, qw, sc, bias, out);
}

// round 11
// speedup vs baseline: 1.1078x; 1.1078x over previous
#include <cuda_runtime.h>
#include <cuda_fp16.h>
#include <cstdint>

// ---------------------------------------------------------------------------
// W4A16 grouped GEMM: out[32,28672] = x[32,8192] @ dequant(qweight) + bias
//   qweight int32 [K/8, N]: 8 int4 nibbles per word along K, zero-point 8
//   x / scales / bias fp16-origin delivered as f32; output f32.
//
// R11: NT=256 per CTA, 256 threads (8 warps x 32 n-cols each -> same W/NT
// LDSM-duplication ratio as R7, the best config), split-K x8, fused last-CTA
// reduction. Grid (112, 8) = 896 CTAs -> 3 CTAs/SM (85-reg cap) = 24 warps/SM,
// 2.0 even waves. R10 root cause fixed: 8 warps x 16n doubled per-work A-frag
// (LDSM) traffic -> L1 70%; restoring 32n/warp halves it back.
//
// Inner math unchanged (R7-verified): mma.sync.m16n8k16 + ldmatrix; qweight
// words LDS-broadcast, dequantized into B frags via byte_perm + magic-bias +
// exact HSUB2{1032,1152} / HMUL2{s,s/16} -> single fp16 rounding per weight.
// ---------------------------------------------------------------------------

static constexpr int MDIM    = 32;
static constexpr int KDIM    = 8192;
static constexpr int NDIM    = 28672;
static constexpr int NT      = 256;                 // n per CTA tile
static constexpr int KC      = 64;                  // k per chunk
static constexpr int KSPLIT  = 8;
static constexpr int CPS     = KDIM / KC / KSPLIT;  // 16 chunks per split
static constexpr int NTILES  = NDIM / NT;           // 112
static constexpr int THREADS = 256;                 // 8 warps
static constexpr int XSTRIDE = 144;                 // bytes per x row in SMEM

__device__ float g_scratch[KSPLIT * MDIM * NDIM];   // 29.36 MB partials
__device__ int   g_cnt[NTILES];                     // zero-init; reset after use

// --------------------------- PTX helpers -----------------------------------

__device__ __forceinline__ uint32_t smem_u32(const void* p) {
    uint32_t a;
    asm("{ .reg .u64 t; cvta.to.shared.u64 t, %1; cvt.u32.u64 %0, t; }"
        : "=r"(a) : "l"(p));
    return a;
}

__device__ __forceinline__ void ldmatrix_x4(uint32_t* r, uint32_t addr) {
    asm volatile(
        "ldmatrix.sync.aligned.m8n8.x4.shared.b16 {%0,%1,%2,%3}, [%4];"
        : "=r"(r[0]), "=r"(r[1]), "=r"(r[2]), "=r"(r[3]) : "r"(addr));
}

__device__ __forceinline__ void mma_16816(float* c, const uint32_t* a,
                                          uint32_t b0, uint32_t b1) {
    asm volatile(
        "mma.sync.aligned.m16n8k16.row.col.f32.f16.f16.f32 "
        "{%0,%1,%2,%3}, {%4,%5,%6,%7}, {%8,%9}, {%0,%1,%2,%3};"
        : "+f"(c[0]), "+f"(c[1]), "+f"(c[2]), "+f"(c[3])
        : "r"(a[0]), "r"(a[1]), "r"(a[2]), "r"(a[3]), "r"(b0), "r"(b1));
}

__device__ __forceinline__ uint32_t pack_h2(float a, float b) {
    __half2 h = __floats2half2_rn(a, b);
    return *reinterpret_cast<uint32_t*>(&h);
}

// --------------------------- dequant ---------------------------------------
// Byte t of word w holds (k=2t lo-nibble, k=2t+1 hi-nibble). byte_perm
// replicates byte t into bytes 0,2; mask+OR builds {1024+n_lo, 1024+16*n_hi};
// exact HSUB2 {1032,1152} then HMUL2 {s, s/16} -> {(n_lo-8)s, (n_hi-8)s}.
__device__ __forceinline__ uint32_t dq_pair(uint32_t w, uint32_t sel, uint32_t mul2u) {
    const uint32_t SUBC = 0x64806408u;  // half2 {1032, 1152}
    uint32_t v = __byte_perm(w, 0, sel);
    uint32_t p = (v & 0x00F0000Fu) | 0x64006400u;
    __half2 h = __hmul2(__hsub2(*reinterpret_cast<__half2*>(&p),
                                *reinterpret_cast<const __half2*>(&SUBC)),
                        *reinterpret_cast<__half2*>(&mul2u));
    return *reinterpret_cast<uint32_t*>(&h);
}

// --------------------------- prefetch fragment ------------------------------
// 256 threads stage a 256n x 64k chunk:
//   qweight: 8 rows x 256 words; thread -> row tid>>5, words (tid&31)*4, +128
//   x:       32 rows x 64 k f32 -> f16; thread -> row tid>>3, 8 k-values
//   scales:  256 cols, 1 per thread

struct Frag {
    uint4    qa, qb;     // 8 qweight words
    uint32_t xh[4];      // 8 halfs of x
    float    sc;         // scale
};

__device__ __forceinline__ Frag load_frag(int c, const uint4* __restrict__ qw4,
                                          const float4* __restrict__ x4,
                                          const float* __restrict__ scales,
                                          int tid, int n0) {
    Frag f;
    int qi = (c * 8 + (tid >> 5)) * (NDIM / 4) + (n0 >> 2) + (tid & 31);
    f.qa = qw4[qi];
    f.qb = qw4[qi + 32];                       // +128 words
    int xi = (tid >> 3) * (KDIM / 4) + c * 16 + (tid & 7) * 2;
    float4 a0 = x4[xi], a1 = x4[xi + 1];
    f.xh[0] = pack_h2(a0.x, a0.y); f.xh[1] = pack_h2(a0.z, a0.w);
    f.xh[2] = pack_h2(a1.x, a1.y); f.xh[3] = pack_h2(a1.z, a1.w);
    f.sc = scales[(c >> 1) * NDIM + n0 + tid];
    return f;
}

// --------------------------- main kernel ------------------------------------

__global__ void __launch_bounds__(THREADS, 3)
w4a16_partial_kernel(const float* __restrict__ x,
                     const uint32_t* __restrict__ qweight,
                     const float* __restrict__ scales,
                     const float* __restrict__ bias,
                     float* __restrict__ out) {
    __shared__ uint32_t s_qw[2][8 * 256];                    // 16 KB
    __shared__ __align__(16) uint8_t s_x[2][32 * XSTRIDE];   // 9 KB
    __shared__ __half s_sc[2][256];                          // 1 KB
    __shared__ int s_last;

    const int tid  = threadIdx.x;
    const int lane = tid & 31;
    const int wid  = tid >> 5;                   // 0..7
    const int tile = blockIdx.x;
    const int n0   = tile * NT;
    const int ks   = blockIdx.y;
    const int c0   = ks * CPS;
    const int t4   = lane & 3;
    const uint32_t sel = 0x4040u + (uint32_t)t4 * 0x0101u;

    int nl[4];
#pragma unroll
    for (int j = 0; j < 4; ++j) nl[j] = wid * 32 + (lane >> 2) + 8 * j;

    const uint4*  qw4 = reinterpret_cast<const uint4*>(qweight);
    const float4* x4  = reinterpret_cast<const float4*>(x);
    const __half one16 = __ushort_as_half(0x2C00);   // 1/16

    uint32_t* qdst = &s_qw[0][(tid >> 5) * 256 + (tid & 31) * 4];
    uint8_t*  xdst = &s_x[0][(tid >> 3) * XSTRIDE + (tid & 7) * 16];
    const uint32_t xm_base = smem_u32(&s_x[0][0]) +
                             (uint32_t)(lane & 15) * XSTRIDE + (uint32_t)(lane >> 4) * 16;

    float acc[2][4][4];
#pragma unroll
    for (int mt = 0; mt < 2; ++mt)
#pragma unroll
        for (int j = 0; j < 4; ++j)
#pragma unroll
            for (int r = 0; r < 4; ++r) acc[mt][j][r] = 0.0f;

    // prologue: stage chunk 0 into buf0, prefetch chunk 1
    {
        Frag f0 = load_frag(c0, qw4, x4, scales, tid, n0);
        *reinterpret_cast<uint4*>(qdst)       = f0.qa;
        *reinterpret_cast<uint4*>(qdst + 128) = f0.qb;
        *reinterpret_cast<uint4*>(xdst)       = *reinterpret_cast<uint4*>(&f0.xh[0]);
        s_sc[0][tid] = __float2half(f0.sc);
    }
    Frag pf = load_frag(c0 + 1, qw4, x4, scales, tid, n0);

    for (int ci = 0; ci < CPS; ++ci) {
        const int buf = ci & 1;
        __syncthreads();   // buf valid for compute; buf^1 free for store

        // store chunk ci+1 into buf^1 (final iteration's store never read)
        {
            uint32_t* qd = qdst + (buf ^ 1) * (8 * 256);
            *reinterpret_cast<uint4*>(qd)       = pf.qa;
            *reinterpret_cast<uint4*>(qd + 128) = pf.qb;
            *reinterpret_cast<uint4*>(xdst + (buf ^ 1) * (32 * XSTRIDE)) =
                *reinterpret_cast<uint4*>(&pf.xh[0]);
            s_sc[buf ^ 1][tid] = __float2half(pf.sc);
        }
        // prefetch chunk ci+2 (wrap within split; never consumed when wrapped)
        pf = load_frag(c0 + ((ci + 2) & (CPS - 1)), qw4, x4, scales, tid, n0);

        // compute chunk ci from buf
        uint32_t mul2[4];
#pragma unroll
        for (int j = 0; j < 4; ++j) {
            __half s = s_sc[buf][nl[j]];
            __half2 m = __halves2half2(s, __hmul(s, one16));
            mul2[j] = *reinterpret_cast<uint32_t*>(&m);
        }
        const uint32_t* qs = &s_qw[buf][0];
        const uint32_t xb = xm_base + (uint32_t)buf * (32 * XSTRIDE);

#pragma unroll
        for (int s4 = 0; s4 < 4; ++s4) {
            uint32_t a0[4], a1[4];
            ldmatrix_x4(a0, xb + s4 * 32);                    // m rows 0-15
            ldmatrix_x4(a1, xb + s4 * 32 + 16 * XSTRIDE);     // m rows 16-31
#pragma unroll
            for (int j = 0; j < 4; ++j) {
                uint32_t w0 = qs[(2 * s4)     * 256 + nl[j]];
                uint32_t w1 = qs[(2 * s4 + 1) * 256 + nl[j]];
                uint32_t b0 = dq_pair(w0, sel, mul2[j]);      // k = 2t, 2t+1
                uint32_t b1 = dq_pair(w1, sel, mul2[j]);      // k = 2t+8, 2t+9
                mma_16816(acc[0][j], a0, b0, b1);
                mma_16816(acc[1][j], a1, b0, b1);
            }
        }
    }

    // partial epilogue: raw f32 sums to scratch[ks][m][n]
    float* sp = g_scratch + ks * (MDIM * NDIM);
#pragma unroll
    for (int j = 0; j < 4; ++j) {
        const int n = n0 + wid * 32 + j * 8 + 2 * t4;
#pragma unroll
        for (int mt = 0; mt < 2; ++mt) {
            const int m0 = mt * 16 + (lane >> 2);
            float2 v01 = { acc[mt][j][0], acc[mt][j][1] };
            float2 v23 = { acc[mt][j][2], acc[mt][j][3] };
            *reinterpret_cast<float2*>(sp + m0 * NDIM + n)       = v01;
            *reinterpret_cast<float2*>(sp + (m0 + 8) * NDIM + n) = v23;
        }
    }

    // ---- fused reduction: last CTA of this tile sums the 8 partials --------
    __threadfence();
    if (tid == 0) {
        int old = atomicAdd(&g_cnt[tile], 1);
        s_last = (old == KSPLIT - 1);
    }
    __syncthreads();
    if (!s_last) return;

    if (tid == 0) g_cnt[tile] = 0;   // reset for next launch / graph replay
    __threadfence();                 // acquire: counter observation -> loads

    const int n = n0 + tid;          // 256 threads : 256 columns
    const __half hb = __float2half(bias[n]);
    const float* sp0 = g_scratch + n;
#pragma unroll 4
    for (int m = 0; m < MDIM; ++m) {
        float s = 0.0f;
#pragma unroll
        for (int k = 0; k < KSPLIT; ++k)
            s += sp0[(k * MDIM + m) * NDIM];
        out[m * NDIM + n] = __half2float(__hadd(__float2half(s), hb));
    }
}

// --------------------------- launch ------------------------------------------

extern "C" void kernel_launch(void* const* d_in, const int* in_sizes, int n_in,
                              void* d_out, int out_size) {
    (void)out_size;
    const float*    x    = nullptr;   // 262144
    const uint32_t* qw   = nullptr;   // 29360128
    const float*    sc   = nullptr;   // 1835008
    const float*    bias = nullptr;   // 28672
    for (int i = 0; i < n_in; ++i) {
        switch (in_sizes[i]) {
            case MDIM * KDIM:            x    = (const float*)d_in[i];    break;
            case (KDIM / 8) * NDIM:      qw   = (const uint32_t*)d_in[i]; break;
            case (KDIM / 128) * NDIM:    sc   = (const float*)d_in[i];    break;
            case NDIM:                   bias = (const float*)d_in[i];    break;
            default: break;
        }
    }
    float* out = (float*)d_out;

    dim3 grid(NTILES, KSPLIT);   // (112, 8) = 896 CTAs
    w4a16_partial_kernel<<<grid, THREADS>>>(x, qw, sc, bias, out);
}

// round 14
// speedup vs baseline: 1.1960x; 1.0796x over previous
#include <cuda_runtime.h>
#include <cuda_fp16.h>
#include <cstdint>

// ---------------------------------------------------------------------------
// W4A16 grouped GEMM: out[32,28672] = x[32,8192] @ dequant(qweight) + bias
//   qweight int32 [K/8, N]: 8 int4 nibbles per word along K, zero-point 8
//   x / scales / bias fp16-origin delivered as f32; output f32.
//
// R12: staging registers eliminated via cp.async (LDGSTS).
//   - pre-kernel converts x f32 -> f16 once into g_xf16 (512 KB, L2-resident)
//   - main kernel stages qweight (2x16B), x-f16 (2x16B), scale (4B) per
//     thread per chunk with cp.async into a 3-buffer ring; one barrier/chunk
//     (issue ci+2 -> compute ci -> wait_group 1 -> sync).
//   - no prefetch Frag -> natural regs ~70, UNCAPPED: 6-7 CTAs/SM without
//     spills (R8-R11 regressions all traced to reg caps / spills / LDSM dup).
//   - tile config = R7 optimum: 128 thr, NT=128, W/NT=4/128, split-K x8,
//     fused last-CTA reduction.
// Math unchanged: mma.sync.m16n8k16 + ldmatrix; dequant via byte_perm +
// magic-bias + exact HSUB2{1032,1152}/HMUL2{s,s/16} (one fp16 rounding/weight).
// ---------------------------------------------------------------------------

static constexpr int MDIM    = 32;
static constexpr int KDIM    = 8192;
static constexpr int NDIM    = 28672;
static constexpr int NT      = 128;                 // n per CTA tile
static constexpr int KC      = 64;                  // k per chunk
static constexpr int KSPLIT  = 8;
static constexpr int CPS     = KDIM / KC / KSPLIT;  // 16 chunks per split
static constexpr int NTILES  = NDIM / NT;           // 224
static constexpr int THREADS = 128;
static constexpr int XSTRIDE = 144;                 // bytes per x row in SMEM
static constexpr int NBUF    = 3;

__device__ __half g_xf16[MDIM * KDIM];              // 512 KB x in fp16
__device__ float  g_scratch[KSPLIT * MDIM * NDIM];  // 29.36 MB partials
__device__ int    g_cnt[NTILES];                    // zero-init; reset in-kernel

// --------------------------- PTX helpers -----------------------------------

__device__ __forceinline__ uint32_t smem_u32(const void* p) {
    uint32_t a;
    asm("{ .reg .u64 t; cvta.to.shared.u64 t, %1; cvt.u32.u64 %0, t; }"
        : "=r"(a) : "l"(p));
    return a;
}

__device__ __forceinline__ void cp16(uint32_t dst, const void* src) {
    asm volatile("cp.async.cg.shared.global [%0], [%1], 16;"
                 :: "r"(dst), "l"(src) : "memory");
}
__device__ __forceinline__ void cp4(uint32_t dst, const void* src) {
    asm volatile("cp.async.ca.shared.global [%0], [%1], 4;"
                 :: "r"(dst), "l"(src) : "memory");
}
__device__ __forceinline__ void cp_commit() {
    asm volatile("cp.async.commit_group;" ::: "memory");
}
__device__ __forceinline__ void cp_wait1() {
    asm volatile("cp.async.wait_group 1;" ::: "memory");
}

__device__ __forceinline__ void ldmatrix_x4(uint32_t* r, uint32_t addr) {
    asm volatile(
        "ldmatrix.sync.aligned.m8n8.x4.shared.b16 {%0,%1,%2,%3}, [%4];"
        : "=r"(r[0]), "=r"(r[1]), "=r"(r[2]), "=r"(r[3]) : "r"(addr));
}

__device__ __forceinline__ void mma_16816(float* c, const uint32_t* a,
                                          uint32_t b0, uint32_t b1) {
    asm volatile(
        "mma.sync.aligned.m16n8k16.row.col.f32.f16.f16.f32 "
        "{%0,%1,%2,%3}, {%4,%5,%6,%7}, {%8,%9}, {%0,%1,%2,%3};"
        : "+f"(c[0]), "+f"(c[1]), "+f"(c[2]), "+f"(c[3])
        : "r"(a[0]), "r"(a[1]), "r"(a[2]), "r"(a[3]), "r"(b0), "r"(b1));
}

// --------------------------- dequant ---------------------------------------
// Byte t of word w holds (k=2t lo-nibble, k=2t+1 hi-nibble). byte_perm
// replicates byte t into bytes 0,2; mask+OR builds {1024+n_lo, 1024+16*n_hi};
// exact HSUB2 {1032,1152} then HMUL2 {s, s/16} -> {(n_lo-8)s, (n_hi-8)s}.
__device__ __forceinline__ uint32_t dq_pair(uint32_t w, uint32_t sel, uint32_t mul2u) {
    const uint32_t SUBC = 0x64806408u;  // half2 {1032, 1152}
    uint32_t v = __byte_perm(w, 0, sel);
    uint32_t p = (v & 0x00F0000Fu) | 0x64006400u;
    __half2 h = __hmul2(__hsub2(*reinterpret_cast<__half2*>(&p),
                                *reinterpret_cast<const __half2*>(&SUBC)),
                        *reinterpret_cast<__half2*>(&mul2u));
    return *reinterpret_cast<uint32_t*>(&h);
}

// --------------------------- x convert pre-kernel ---------------------------

__global__ void __launch_bounds__(256)
x_convert_kernel(const float* __restrict__ x) {
    const int i = (blockIdx.x * 256 + threadIdx.x) * 4;
    float4 v = *reinterpret_cast<const float4*>(x + i);
    __half2 h0 = __floats2half2_rn(v.x, v.y);
    __half2 h1 = __floats2half2_rn(v.z, v.w);
    uint2 u = { *reinterpret_cast<uint32_t*>(&h0), *reinterpret_cast<uint32_t*>(&h1) };
    *reinterpret_cast<uint2*>(&g_xf16[i]) = u;
}

// --------------------------- main kernel ------------------------------------

__global__ void __launch_bounds__(THREADS)
w4a16_partial_kernel(const uint32_t* __restrict__ qweight,
                     const float* __restrict__ scales,
                     const float* __restrict__ bias,
                     float* __restrict__ out) {
    __shared__ uint32_t s_qw[NBUF][8 * 128];                    // 12 KB
    __shared__ __align__(16) uint8_t s_x[NBUF][32 * XSTRIDE];   // 13.5 KB
    __shared__ float s_sc[NBUF][128];                           // 1.5 KB
    __shared__ int s_last;

    const int tid  = threadIdx.x;
    const int lane = tid & 31;
    const int wid  = tid >> 5;
    const int tile = blockIdx.x;
    const int n0   = tile * NT;
    const int ks   = blockIdx.y;
    const int c0   = ks * CPS;
    const int t4   = lane & 3;
    const uint32_t sel = 0x4040u + (uint32_t)t4 * 0x0101u;

    int nl[4];
#pragma unroll
    for (int j = 0; j < 4; ++j) nl[j] = wid * 32 + (lane >> 2) + 8 * j;

    const __half one16 = __ushort_as_half(0x2C00);   // 1/16

    // per-thread cp.async source bases (chunk offsets added per stage)
    const uint32_t* qsrc0 = qweight + (tid >> 4) * NDIM + n0 + (tid & 15) * 8;
    const __half*   xsrc0 = g_xf16 + (tid >> 2) * KDIM + (tid & 3) * 16;
    const float*    ssrc0 = scales + n0 + tid;

    // per-thread cp.async SMEM destinations (buf 0 offsets)
    const uint32_t qdst0 = smem_u32(&s_qw[0][0]) + ((tid >> 4) * 128 + (tid & 15) * 8) * 4;
    const uint32_t xdst0 = smem_u32(&s_x[0][0]) + (tid >> 2) * XSTRIDE + (tid & 3) * 32;
    const uint32_t sdst0 = smem_u32(&s_sc[0][0]) + tid * 4;

    const uint32_t xm_base = smem_u32(&s_x[0][0]) +
                             (uint32_t)(lane & 15) * XSTRIDE + (uint32_t)(lane >> 4) * 16;

    float acc[2][4][4];
#pragma unroll
    for (int mt = 0; mt < 2; ++mt)
#pragma unroll
        for (int j = 0; j < 4; ++j)
#pragma unroll
            for (int r = 0; r < 4; ++r) acc[mt][j][r] = 0.0f;

    // stage(chunk c, buffer b): 5 cp.asyncs + commit
    auto stage = [&](int c, int b) {
        const uint32_t* qs = qsrc0 + c * 8 * NDIM;
        uint32_t qd = qdst0 + b * (8 * 128 * 4);
        cp16(qd,      qs);
        cp16(qd + 16, qs + 4);
        const __half* xs = xsrc0 + c * 64;
        uint32_t xd = xdst0 + b * (32 * XSTRIDE);
        cp16(xd,      xs);
        cp16(xd + 16, xs + 8);
        cp4(sdst0 + b * (128 * 4), ssrc0 + (c >> 1) * NDIM);
        cp_commit();
    };

    // prologue: chunks 0,1 in flight; wait for chunk 0
    stage(c0,     0);
    stage(c0 + 1, 1);
    cp_wait1();
    __syncthreads();

    int buf = 0, nbuf3 = 2;          // buffer of chunk ci; buffer of chunk ci+2
    for (int ci = 0; ci < CPS; ++ci) {
        // issue chunk ci+2 into the buffer last read at iter ci-1 (safe: synced)
        stage(c0 + ((ci + 2) & (CPS - 1)), nbuf3);

        // compute chunk ci from buf
        uint32_t mul2[4];
#pragma unroll
        for (int j = 0; j < 4; ++j) {
            __half s = __float2half(s_sc[buf][nl[j]]);
            __half2 m = __halves2half2(s, __hmul(s, one16));
            mul2[j] = *reinterpret_cast<uint32_t*>(&m);
        }
        const uint32_t* qs = &s_qw[buf][0];
        const uint32_t xb = xm_base + (uint32_t)buf * (32 * XSTRIDE);

#pragma unroll
        for (int s4 = 0; s4 < 4; ++s4) {
            uint32_t a0[4], a1[4];
            ldmatrix_x4(a0, xb + s4 * 32);                    // m rows 0-15
            ldmatrix_x4(a1, xb + s4 * 32 + 16 * XSTRIDE);     // m rows 16-31
#pragma unroll
            for (int j = 0; j < 4; ++j) {
                uint32_t w0 = qs[(2 * s4)     * 128 + nl[j]];
                uint32_t w1 = qs[(2 * s4 + 1) * 128 + nl[j]];
                uint32_t b0 = dq_pair(w0, sel, mul2[j]);      // k = 2t, 2t+1
                uint32_t b1 = dq_pair(w1, sel, mul2[j]);      // k = 2t+8, 2t+9
                mma_16816(acc[0][j], a0, b0, b1);
                mma_16816(acc[1][j], a1, b0, b1);
            }
        }

        cp_wait1();          // chunk ci+1 landed (only ci+2 may remain pending)
        __syncthreads();     // make it visible to all warps
        buf   = (buf == 2) ? 0 : buf + 1;
        nbuf3 = (nbuf3 == 2) ? 0 : nbuf3 + 1;
    }

    // partial epilogue: raw f32 sums to scratch[ks][m][n]
    float* sp = g_scratch + ks * (MDIM * NDIM);
#pragma unroll
    for (int j = 0; j < 4; ++j) {
        const int n = n0 + wid * 32 + j * 8 + 2 * t4;
#pragma unroll
        for (int mt = 0; mt < 2; ++mt) {
            const int m0 = mt * 16 + (lane >> 2);
            float2 v01 = { acc[mt][j][0], acc[mt][j][1] };
            float2 v23 = { acc[mt][j][2], acc[mt][j][3] };
            *reinterpret_cast<float2*>(sp + m0 * NDIM + n)       = v01;
            *reinterpret_cast<float2*>(sp + (m0 + 8) * NDIM + n) = v23;
        }
    }

    // ---- fused reduction: last CTA of this tile sums the 8 partials --------
    __threadfence();
    if (tid == 0) {
        int old = atomicAdd(&g_cnt[tile], 1);
        s_last = (old == KSPLIT - 1);
    }
    __syncthreads();
    if (!s_last) return;

    if (tid == 0) g_cnt[tile] = 0;   // reset for next launch / graph replay
    __threadfence();                 // acquire: counter observation -> loads

    const int n = n0 + tid;          // 128 threads : 128 columns
    const __half hb = __float2half(bias[n]);
    const float* sp0 = g_scratch + n;
#pragma unroll 4
    for (int m = 0; m < MDIM; ++m) {
        float s = 0.0f;
#pragma unroll
        for (int k = 0; k < KSPLIT; ++k)
            s += sp0[(k * MDIM + m) * NDIM];
        out[m * NDIM + n] = __half2float(__hadd(__float2half(s), hb));
    }
}

// --------------------------- launch ------------------------------------------

extern "C" void kernel_launch(void* const* d_in, const int* in_sizes, int n_in,
                              void* d_out, int out_size) {
    (void)out_size;
    const float*    x    = nullptr;   // 262144
    const uint32_t* qw   = nullptr;   // 29360128
    const float*    sc   = nullptr;   // 1835008
    const float*    bias = nullptr;   // 28672
    for (int i = 0; i < n_in; ++i) {
        switch (in_sizes[i]) {
            case MDIM * KDIM:            x    = (const float*)d_in[i];    break;
            case (KDIM / 8) * NDIM:      qw   = (const uint32_t*)d_in[i]; break;
            case (KDIM / 128) * NDIM:    sc   = (const float*)d_in[i];    break;
            case NDIM:                   bias = (const float*)d_in[i];    break;
            default: break;
        }
    }
    float* out = (float*)d_out;

    x_convert_kernel<<<MDIM * KDIM / (256 * 4), 256>>>(x);

    dim3 grid(NTILES, KSPLIT);   // (224, 8) = 1792 CTAs
    w4a16_partial_kernel<<<grid, THREADS>>>(qw, sc, bias, out);
}

// round 15
// speedup vs baseline: 1.3100x; 1.0953x over previous
#include <cuda_runtime.h>
#include <cuda_fp16.h>
#include <cstdint>

// ---------------------------------------------------------------------------
// W4A16 grouped GEMM: out[32,28672] = x[32,8192] @ dequant(qweight) + bias
//   qweight int32 [K/8, N]: 8 int4 nibbles per word along K, zero-point 8
//   x / scales / bias fp16-origin delivered as f32; output f32.
//
// R14: single-wave residency. KSPLIT=4 -> grid (224,4)=896 CTAs = 6.05/SM,
// all resident in ONE wave under the 7-CTA/SM register limit (72 regs,
// NBUF=3 SMEM 27 KB). Removes wave churn + ragged tail behind R12's
// occ=30.8%. Fused-reduce fan-in 8->4. Everything else = R12:
//   - cp.async 3-buffer ring, distance-2 prefetch, one barrier per chunk
//   - pre-kernel converts x f32->f16 into g_xf16 (512 KB, L2-resident)
//   - 128 thr, NT=128, W/NT=4/128 (minimal LDSM duplication)
//   - mma.sync.m16n8k16 + ldmatrix; dequant via byte_perm + magic-bias +
//     exact HSUB2{1032,1152}/HMUL2{s,s/16} (one fp16 rounding per weight)
// ---------------------------------------------------------------------------

static constexpr int MDIM    = 32;
static constexpr int KDIM    = 8192;
static constexpr int NDIM    = 28672;
static constexpr int NT      = 128;                 // n per CTA tile
static constexpr int KC      = 64;                  // k per chunk
static constexpr int KSPLIT  = 4;
static constexpr int CPS     = KDIM / KC / KSPLIT;  // 32 chunks per split
static constexpr int NTILES  = NDIM / NT;           // 224
static constexpr int THREADS = 128;
static constexpr int XSTRIDE = 144;                 // bytes per x row in SMEM
static constexpr int NBUF    = 3;

__device__ __half g_xf16[MDIM * KDIM];              // 512 KB x in fp16
__device__ float  g_scratch[KSPLIT * MDIM * NDIM];  // 14.7 MB partials
__device__ int    g_cnt[NTILES];                    // zero-init; reset in-kernel

// --------------------------- PTX helpers -----------------------------------

__device__ __forceinline__ uint32_t smem_u32(const void* p) {
    uint32_t a;
    asm("{ .reg .u64 t; cvta.to.shared.u64 t, %1; cvt.u32.u64 %0, t; }"
        : "=r"(a) : "l"(p));
    return a;
}

__device__ __forceinline__ void cp16(uint32_t dst, const void* src) {
    asm volatile("cp.async.cg.shared.global [%0], [%1], 16;"
                 :: "r"(dst), "l"(src) : "memory");
}
__device__ __forceinline__ void cp4(uint32_t dst, const void* src) {
    asm volatile("cp.async.ca.shared.global [%0], [%1], 4;"
                 :: "r"(dst), "l"(src) : "memory");
}
__device__ __forceinline__ void cp_commit() {
    asm volatile("cp.async.commit_group;" ::: "memory");
}
__device__ __forceinline__ void cp_wait1() {
    asm volatile("cp.async.wait_group 1;" ::: "memory");
}

__device__ __forceinline__ void ldmatrix_x4(uint32_t* r, uint32_t addr) {
    asm volatile(
        "ldmatrix.sync.aligned.m8n8.x4.shared.b16 {%0,%1,%2,%3}, [%4];"
        : "=r"(r[0]), "=r"(r[1]), "=r"(r[2]), "=r"(r[3]) : "r"(addr));
}

__device__ __forceinline__ void mma_16816(float* c, const uint32_t* a,
                                          uint32_t b0, uint32_t b1) {
    asm volatile(
        "mma.sync.aligned.m16n8k16.row.col.f32.f16.f16.f32 "
        "{%0,%1,%2,%3}, {%4,%5,%6,%7}, {%8,%9}, {%0,%1,%2,%3};"
        : "+f"(c[0]), "+f"(c[1]), "+f"(c[2]), "+f"(c[3])
        : "r"(a[0]), "r"(a[1]), "r"(a[2]), "r"(a[3]), "r"(b0), "r"(b1));
}

// --------------------------- dequant ---------------------------------------
// Byte t of word w holds (k=2t lo-nibble, k=2t+1 hi-nibble). byte_perm
// replicates byte t into bytes 0,2; mask+OR builds {1024+n_lo, 1024+16*n_hi};
// exact HSUB2 {1032,1152} then HMUL2 {s, s/16} -> {(n_lo-8)s, (n_hi-8)s}.
__device__ __forceinline__ uint32_t dq_pair(uint32_t w, uint32_t sel, uint32_t mul2u) {
    const uint32_t SUBC = 0x64806408u;  // half2 {1032, 1152}
    uint32_t v = __byte_perm(w, 0, sel);
    uint32_t p = (v & 0x00F0000Fu) | 0x64006400u;
    __half2 h = __hmul2(__hsub2(*reinterpret_cast<__half2*>(&p),
                                *reinterpret_cast<const __half2*>(&SUBC)),
                        *reinterpret_cast<__half2*>(&mul2u));
    return *reinterpret_cast<uint32_t*>(&h);
}

// --------------------------- x convert pre-kernel ---------------------------

__global__ void __launch_bounds__(256)
x_convert_kernel(const float* __restrict__ x) {
    const int i = (blockIdx.x * 256 + threadIdx.x) * 4;
    float4 v = *reinterpret_cast<const float4*>(x + i);
    __half2 h0 = __floats2half2_rn(v.x, v.y);
    __half2 h1 = __floats2half2_rn(v.z, v.w);
    uint2 u = { *reinterpret_cast<uint32_t*>(&h0), *reinterpret_cast<uint32_t*>(&h1) };
    *reinterpret_cast<uint2*>(&g_xf16[i]) = u;
}

// --------------------------- main kernel ------------------------------------

__global__ void __launch_bounds__(THREADS)
w4a16_partial_kernel(const uint32_t* __restrict__ qweight,
                     const float* __restrict__ scales,
                     const float* __restrict__ bias,
                     float* __restrict__ out) {
    __shared__ uint32_t s_qw[NBUF][8 * 128];                    // 12 KB
    __shared__ __align__(16) uint8_t s_x[NBUF][32 * XSTRIDE];   // 13.5 KB
    __shared__ float s_sc[NBUF][128];                           // 1.5 KB
    __shared__ int s_last;

    const int tid  = threadIdx.x;
    const int lane = tid & 31;
    const int wid  = tid >> 5;
    const int tile = blockIdx.x;
    const int n0   = tile * NT;
    const int ks   = blockIdx.y;
    const int c0   = ks * CPS;
    const int t4   = lane & 3;
    const uint32_t sel = 0x4040u + (uint32_t)t4 * 0x0101u;

    int nl[4];
#pragma unroll
    for (int j = 0; j < 4; ++j) nl[j] = wid * 32 + (lane >> 2) + 8 * j;

    const __half one16 = __ushort_as_half(0x2C00);   // 1/16

    // per-thread cp.async source bases (chunk offsets added per stage)
    const uint32_t* qsrc0 = qweight + (tid >> 4) * NDIM + n0 + (tid & 15) * 8;
    const __half*   xsrc0 = g_xf16 + (tid >> 2) * KDIM + (tid & 3) * 16;
    const float*    ssrc0 = scales + n0 + tid;

    // per-thread cp.async SMEM destinations (buf 0 offsets)
    const uint32_t qdst0 = smem_u32(&s_qw[0][0]) + ((tid >> 4) * 128 + (tid & 15) * 8) * 4;
    const uint32_t xdst0 = smem_u32(&s_x[0][0]) + (tid >> 2) * XSTRIDE + (tid & 3) * 32;
    const uint32_t sdst0 = smem_u32(&s_sc[0][0]) + tid * 4;

    const uint32_t xm_base = smem_u32(&s_x[0][0]) +
                             (uint32_t)(lane & 15) * XSTRIDE + (uint32_t)(lane >> 4) * 16;

    float acc[2][4][4];
#pragma unroll
    for (int mt = 0; mt < 2; ++mt)
#pragma unroll
        for (int j = 0; j < 4; ++j)
#pragma unroll
            for (int r = 0; r < 4; ++r) acc[mt][j][r] = 0.0f;

    // stage(chunk c, buffer b): 5 cp.asyncs + commit
    auto stage = [&](int c, int b) {
        const uint32_t* qs = qsrc0 + c * 8 * NDIM;
        uint32_t qd = qdst0 + b * (8 * 128 * 4);
        cp16(qd,      qs);
        cp16(qd + 16, qs + 4);
        const __half* xs = xsrc0 + c * 64;
        uint32_t xd = xdst0 + b * (32 * XSTRIDE);
        cp16(xd,      xs);
        cp16(xd + 16, xs + 8);
        cp4(sdst0 + b * (128 * 4), ssrc0 + (c >> 1) * NDIM);
        cp_commit();
    };

    // prologue: chunks 0,1 in flight; wait for chunk 0
    stage(c0,     0);
    stage(c0 + 1, 1);
    cp_wait1();
    __syncthreads();

    int buf = 0, nbuf3 = 2;          // buffer of chunk ci; buffer of chunk ci+2
    for (int ci = 0; ci < CPS; ++ci) {
        // issue chunk ci+2 into the buffer last read at iter ci-1 (safe: synced)
        stage(c0 + ((ci + 2) & (CPS - 1)), nbuf3);

        // compute chunk ci from buf
        uint32_t mul2[4];
#pragma unroll
        for (int j = 0; j < 4; ++j) {
            __half s = __float2half(s_sc[buf][nl[j]]);
            __half2 m = __halves2half2(s, __hmul(s, one16));
            mul2[j] = *reinterpret_cast<uint32_t*>(&m);
        }
        const uint32_t* qs = &s_qw[buf][0];
        const uint32_t xb = xm_base + (uint32_t)buf * (32 * XSTRIDE);

#pragma unroll
        for (int s4 = 0; s4 < 4; ++s4) {
            uint32_t a0[4], a1[4];
            ldmatrix_x4(a0, xb + s4 * 32);                    // m rows 0-15
            ldmatrix_x4(a1, xb + s4 * 32 + 16 * XSTRIDE);     // m rows 16-31
#pragma unroll
            for (int j = 0; j < 4; ++j) {
                uint32_t w0 = qs[(2 * s4)     * 128 + nl[j]];
                uint32_t w1 = qs[(2 * s4 + 1) * 128 + nl[j]];
                uint32_t b0 = dq_pair(w0, sel, mul2[j]);      // k = 2t, 2t+1
                uint32_t b1 = dq_pair(w1, sel, mul2[j]);      // k = 2t+8, 2t+9
                mma_16816(acc[0][j], a0, b0, b1);
                mma_16816(acc[1][j], a1, b0, b1);
            }
        }

        cp_wait1();          // chunk ci+1 landed (only ci+2 may remain pending)
        __syncthreads();     // make it visible to all warps
        buf   = (buf == 2) ? 0 : buf + 1;
        nbuf3 = (nbuf3 == 2) ? 0 : nbuf3 + 1;
    }

    // partial epilogue: raw f32 sums to scratch[ks][m][n]
    float* sp = g_scratch + ks * (MDIM * NDIM);
#pragma unroll
    for (int j = 0; j < 4; ++j) {
        const int n = n0 + wid * 32 + j * 8 + 2 * t4;
#pragma unroll
        for (int mt = 0; mt < 2; ++mt) {
            const int m0 = mt * 16 + (lane >> 2);
            float2 v01 = { acc[mt][j][0], acc[mt][j][1] };
            float2 v23 = { acc[mt][j][2], acc[mt][j][3] };
            *reinterpret_cast<float2*>(sp + m0 * NDIM + n)       = v01;
            *reinterpret_cast<float2*>(sp + (m0 + 8) * NDIM + n) = v23;
        }
    }

    // ---- fused reduction: last CTA of this tile sums the 4 partials --------
    __threadfence();
    if (tid == 0) {
        int old = atomicAdd(&g_cnt[tile], 1);
        s_last = (old == KSPLIT - 1);
    }
    __syncthreads();
    if (!s_last) return;

    if (tid == 0) g_cnt[tile] = 0;   // reset for next launch / graph replay
    __threadfence();                 // acquire: counter observation -> loads

    const int n = n0 + tid;          // 128 threads : 128 columns
    const __half hb = __float2half(bias[n]);
    const float* sp0 = g_scratch + n;
#pragma unroll 4
    for (int m = 0; m < MDIM; ++m) {
        float s = 0.0f;
#pragma unroll
        for (int k = 0; k < KSPLIT; ++k)
            s += sp0[(k * MDIM + m) * NDIM];
        out[m * NDIM + n] = __half2float(__hadd(__float2half(s), hb));
    }
}

// --------------------------- launch ------------------------------------------

extern "C" void kernel_launch(void* const* d_in, const int* in_sizes, int n_in,
                              void* d_out, int out_size) {
    (void)out_size;
    const float*    x    = nullptr;   // 262144
    const uint32_t* qw   = nullptr;   // 29360128
    const float*    sc   = nullptr;   // 1835008
    const float*    bias = nullptr;   // 28672
    for (int i = 0; i < n_in; ++i) {
        switch (in_sizes[i]) {
            case MDIM * KDIM:            x    = (const float*)d_in[i];    break;
            case (KDIM / 8) * NDIM:      qw   = (const uint32_t*)d_in[i]; break;
            case (KDIM / 128) * NDIM:    sc   = (const float*)d_in[i];    break;
            case NDIM:                   bias = (const float*)d_in[i];    break;
            default: break;
        }
    }
    float* out = (float*)d_out;

    x_convert_kernel<<<MDIM * KDIM / (256 * 4), 256>>>(x);

    dim3 grid(NTILES, KSPLIT);   // (224, 4) = 896 CTAs -> single wave
    w4a16_partial_kernel<<<grid, THREADS>>>(qw, sc, bias, out);
}